// round 2
// baseline (speedup 1.0000x reference)
#include <cuda_runtime.h>

// ---------------------------------------------------------------------------
// MultiHeadAttention  B=2, S=2048, D_MODEL=1024, H=16, D_K=64
// out tuple: output [B,S,1024]  ++  attn_weights [B,H,S,S]
// ---------------------------------------------------------------------------

#define B_    2
#define S_    2048
#define D_    1024
#define H_    16
#define DK_   64
#define MROWS (B_ * S_)   // 4096
#define BH_   (B_ * H_)   // 32

// Scratch (allocation-free rule: __device__ globals)
__device__ float g_qh[BH_ * S_ * DK_];   // [B,H,S,DK] 16 MB
__device__ float g_kh[BH_ * S_ * DK_];
__device__ float g_vh[BH_ * S_ * DK_];
__device__ float g_ao[MROWS * D_];       // attn_out in [B,S,H*DK] layout
__device__ float g_rmax[BH_ * S_];
__device__ float g_rsum[BH_ * S_];

// ---------------------------------------------------------------------------
// Generic SGEMM:  C = alpha * A @ B^T   (A:[M,K], B:[N,K], row-major)
// 128x128 tile, BK=8, 256 threads, 8x8 per thread.
// LAYOUT 0: C row-major [M,N].  LAYOUT 1: scatter into head layout [B,H,S,DK]
//           (row m -> (b,s), col n -> (h,d)).
// ---------------------------------------------------------------------------
template <int LAYOUT>
__global__ __launch_bounds__(256)
void sgemm_nt(const float* __restrict__ A, const float* __restrict__ B,
              float* __restrict__ C, int M, int N, int K,
              long sA, long sB, long sC, float alpha)
{
    A += (long)blockIdx.z * sA;
    B += (long)blockIdx.z * sB;
    C += (long)blockIdx.z * sC;

    __shared__ float As[8][128];
    __shared__ float Bs[8][128];

    const int tid = threadIdx.x;
    const int tx = tid & 15;        // 0..15  -> col group
    const int ty = tid >> 4;        // 0..15  -> row group
    const int m0 = blockIdx.y * 128;
    const int n0 = blockIdx.x * 128;

    const int lrow = tid >> 1;       // 0..127
    const int lcol = (tid & 1) * 4;  // 0 or 4

    float acc[8][8];
#pragma unroll
    for (int i = 0; i < 8; i++)
#pragma unroll
        for (int j = 0; j < 8; j++) acc[i][j] = 0.0f;

    const float* Aptr = A + (long)(m0 + lrow) * K + lcol;
    const float* Bptr = B + (long)(n0 + lrow) * K + lcol;

    for (int kt = 0; kt < K; kt += 8) {
        const float4 av = *(const float4*)(Aptr + kt);
        const float4 bv = *(const float4*)(Bptr + kt);
        __syncthreads();
        As[lcol + 0][lrow] = av.x; As[lcol + 1][lrow] = av.y;
        As[lcol + 2][lrow] = av.z; As[lcol + 3][lrow] = av.w;
        Bs[lcol + 0][lrow] = bv.x; Bs[lcol + 1][lrow] = bv.y;
        Bs[lcol + 2][lrow] = bv.z; Bs[lcol + 3][lrow] = bv.w;
        __syncthreads();

#pragma unroll
        for (int kk = 0; kk < 8; kk++) {
            float a[8], b[8];
            *(float4*)(a)     = *(const float4*)&As[kk][ty * 8];
            *(float4*)(a + 4) = *(const float4*)&As[kk][ty * 8 + 4];
            *(float4*)(b)     = *(const float4*)&Bs[kk][tx * 8];
            *(float4*)(b + 4) = *(const float4*)&Bs[kk][tx * 8 + 4];
#pragma unroll
            for (int i = 0; i < 8; i++)
#pragma unroll
                for (int j = 0; j < 8; j++)
                    acc[i][j] += a[i] * b[j];
        }
    }

#pragma unroll
    for (int i = 0; i < 8; i++) {
        const int m = m0 + ty * 8 + i;
        if (LAYOUT == 0) {
            float4 v0 = make_float4(acc[i][0] * alpha, acc[i][1] * alpha,
                                    acc[i][2] * alpha, acc[i][3] * alpha);
            float4 v1 = make_float4(acc[i][4] * alpha, acc[i][5] * alpha,
                                    acc[i][6] * alpha, acc[i][7] * alpha);
            *(float4*)(C + (long)m * N + n0 + tx * 8)     = v0;
            *(float4*)(C + (long)m * N + n0 + tx * 8 + 4) = v1;
        } else {
            const int bb = m >> 11;        // m / S_
            const int ss = m & (S_ - 1);
#pragma unroll
            for (int j = 0; j < 8; j++) {
                const int n = n0 + tx * 8 + j;
                const int h = n >> 6;
                const int d = n & 63;
                C[(((long)(bb * H_ + h)) * S_ + ss) * DK_ + d] = acc[i][j] * alpha;
            }
        }
    }
}

// ---------------------------------------------------------------------------
// Row softmax stats: one block per row of attn (B*H*S rows, S_ cols).
// ---------------------------------------------------------------------------
__global__ __launch_bounds__(256)
void softmax_stats(const float* __restrict__ attn,
                   float* __restrict__ rmax, float* __restrict__ rsum)
{
    const long row = blockIdx.x;
    const float* p = attn + row * S_;
    const int t = threadIdx.x;

    __shared__ float red[8];

    float m = -1e30f;
#pragma unroll
    for (int i = t; i < S_; i += 256) m = fmaxf(m, p[i]);
#pragma unroll
    for (int o = 16; o; o >>= 1) m = fmaxf(m, __shfl_xor_sync(0xffffffffu, m, o));
    if ((t & 31) == 0) red[t >> 5] = m;
    __syncthreads();
    float mm = red[0];
#pragma unroll
    for (int i = 1; i < 8; i++) mm = fmaxf(mm, red[i]);
    __syncthreads();  // all threads have mm before red is reused

    float s = 0.0f;
#pragma unroll
    for (int i = t; i < S_; i += 256) s += __expf(p[i] - mm);
#pragma unroll
    for (int o = 16; o; o >>= 1) s += __shfl_xor_sync(0xffffffffu, s, o);
    if ((t & 31) == 0) red[t >> 5] = s;
    __syncthreads();
    if (t == 0) {
        float ss = 0.0f;
#pragma unroll
        for (int i = 0; i < 8; i++) ss += red[i];
        rmax[row] = mm;
        rsum[row] = ss;
    }
}

// ---------------------------------------------------------------------------
// Fused normalize + PV.
// Per (b,h): reads raw scores, writes normalized weights (output!) back,
// and accumulates attn_out = W @ V  into [B,S,H*DK] layout.
// Block: 128 q-rows x 64 (full DK) ; BK = 16 ; 256 threads ; 8x4 per thread.
// ---------------------------------------------------------------------------
__global__ __launch_bounds__(256)
void pv_fused(float* __restrict__ attn, const float* __restrict__ vh,
              const float* __restrict__ rmax, const float* __restrict__ rsum,
              float* __restrict__ ao)
{
    const int bh = blockIdx.z;
    float* Abase = attn + (long)bh * S_ * S_;
    const float* V = vh + (long)bh * S_ * DK_;
    const int m0 = blockIdx.x * 128;

    const int tid = threadIdx.x;
    const int tx = tid & 15;   // n group (x4)
    const int ty = tid >> 4;   // m group (x8)

    __shared__ float Ws[16][136];  // [k][m], padded
    __shared__ float Vs[16][64];   // [k][n]

    const int lr  = tid >> 1;        // row 0..127
    const int lc4 = (tid & 1) * 2;   // float4 slot 0 or 2 (8 floats / thread)

    const int gm = m0 + lr;
    const long rowid = (long)bh * S_ + gm;
    const float mx  = rmax[rowid];
    const float inv = 1.0f / rsum[rowid];
    float* Arow = Abase + (long)gm * S_;

    const int vk = tid >> 4;         // 0..15
    const int vc = (tid & 15) * 4;   // 0..60

    float acc[8][4];
#pragma unroll
    for (int i = 0; i < 8; i++)
#pragma unroll
        for (int j = 0; j < 4; j++) acc[i][j] = 0.0f;

    for (int kt = 0; kt < S_; kt += 16) {
        float4 a0 = *(float4*)(Arow + kt + lc4 * 4);
        float4 a1 = *(float4*)(Arow + kt + lc4 * 4 + 4);
        const float4 vv = *(const float4*)(V + (long)(kt + vk) * DK_ + vc);

        a0.x = __expf(a0.x - mx) * inv;  a0.y = __expf(a0.y - mx) * inv;
        a0.z = __expf(a0.z - mx) * inv;  a0.w = __expf(a0.w - mx) * inv;
        a1.x = __expf(a1.x - mx) * inv;  a1.y = __expf(a1.y - mx) * inv;
        a1.z = __expf(a1.z - mx) * inv;  a1.w = __expf(a1.w - mx) * inv;

        // attn_weights is a kernel output: write the normalized weights back.
        *(float4*)(Arow + kt + lc4 * 4)     = a0;
        *(float4*)(Arow + kt + lc4 * 4 + 4) = a1;

        __syncthreads();
        {
            const int k0 = lc4 * 4;
            Ws[k0 + 0][lr] = a0.x; Ws[k0 + 1][lr] = a0.y;
            Ws[k0 + 2][lr] = a0.z; Ws[k0 + 3][lr] = a0.w;
            Ws[k0 + 4][lr] = a1.x; Ws[k0 + 5][lr] = a1.y;
            Ws[k0 + 6][lr] = a1.z; Ws[k0 + 7][lr] = a1.w;
            *(float4*)&Vs[vk][vc] = vv;
        }
        __syncthreads();

#pragma unroll
        for (int kk = 0; kk < 16; kk++) {
            float a[8], b[4];
            *(float4*)(a)     = *(const float4*)&Ws[kk][ty * 8];
            *(float4*)(a + 4) = *(const float4*)&Ws[kk][ty * 8 + 4];
            *(float4*)(b)     = *(const float4*)&Vs[kk][tx * 4];
#pragma unroll
            for (int i = 0; i < 8; i++)
#pragma unroll
                for (int j = 0; j < 4; j++)
                    acc[i][j] += a[i] * b[j];
        }
    }

    const int bb = bh >> 4;   // bh / H_
    const int hh = bh & 15;
#pragma unroll
    for (int i = 0; i < 8; i++) {
        const int s = m0 + ty * 8 + i;
        float4 v = make_float4(acc[i][0], acc[i][1], acc[i][2], acc[i][3]);
        *(float4*)(ao + ((long)(bb * S_ + s)) * D_ + hh * DK_ + tx * 4) = v;
    }
}

// ---------------------------------------------------------------------------
// Launch
// ---------------------------------------------------------------------------
extern "C" void kernel_launch(void* const* d_in, const int* in_sizes, int n_in,
                              void* d_out, int out_size)
{
    const float* q  = (const float*)d_in[0];
    const float* k  = (const float*)d_in[1];
    const float* v  = (const float*)d_in[2];
    const float* Wq = (const float*)d_in[3];
    const float* Wk = (const float*)d_in[4];
    const float* Wv = (const float*)d_in[5];
    const float* Wo = (const float*)d_in[6];

    float* out  = (float*)d_out;                    // [B,S,1024]
    float* attn = out + (long)MROWS * D_;           // [B,H,S,S]

    float *qh, *kh, *vh, *ao, *rmax, *rsum;
    cudaGetSymbolAddress((void**)&qh,   g_qh);
    cudaGetSymbolAddress((void**)&kh,   g_kh);
    cudaGetSymbolAddress((void**)&vh,   g_vh);
    cudaGetSymbolAddress((void**)&ao,   g_ao);
    cudaGetSymbolAddress((void**)&rmax, g_rmax);
    cudaGetSymbolAddress((void**)&rsum, g_rsum);

    const dim3 tb(256);

    // 1) Q/K/V projections -> head layout  (M=4096, N=1024, K=1024)
    const dim3 gproj(D_ / 128, MROWS / 128, 1);
    sgemm_nt<1><<<gproj, tb>>>(q, Wq, qh, MROWS, D_, D_, 0, 0, 0, 1.0f);
    sgemm_nt<1><<<gproj, tb>>>(k, Wk, kh, MROWS, D_, D_, 0, 0, 0, 1.0f);
    sgemm_nt<1><<<gproj, tb>>>(v, Wv, vh, MROWS, D_, D_, 0, 0, 0, 1.0f);

    // 2) Raw scores = Q K^T / 8  per (b,h), into attn output region (scratch)
    const dim3 gsc(S_ / 128, S_ / 128, BH_);
    sgemm_nt<0><<<gsc, tb>>>(qh, kh, attn, S_, S_, DK_,
                             (long)S_ * DK_, (long)S_ * DK_, (long)S_ * S_,
                             0.125f);

    // 3) Row max / sum-exp
    softmax_stats<<<BH_ * S_, tb>>>(attn, rmax, rsum);

    // 4) Normalize (write weights output) + PV fused
    const dim3 gpv(S_ / 128, 1, BH_);
    pv_fused<<<gpv, tb>>>(attn, vh, rmax, rsum, ao);

    // 5) Output projection  (M=4096, N=1024, K=1024)
    sgemm_nt<0><<<gproj, tb>>>(ao, Wo, out, MROWS, D_, D_, 0, 0, 0, 1.0f);
}